// round 6
// baseline (speedup 1.0000x reference)
#include <cuda_runtime.h>
#include <cstdint>
#include <cstddef>

#define NN 100000
#define EE 1000000
#define DD 64
#define KK 8
#define LL 3

#define SCAN_TPB 1024
#define SCAN_BLOCKS ((NN + SCAN_TPB - 1) / SCAN_TPB)   // 98
#define NBINS 64
#define EPAD (EE + 3 * NN + 64)                        // padded edge capacity

// ---------------- device scratch (statically allocated; no runtime alloc) ----------------
__device__ float g_T[7][(size_t)NN * DD];
__device__ float g_out1[(size_t)NN * DD];
__device__ float g_out2[(size_t)NN * DD];
__device__ float g_xp[(size_t)NN * DD];     // x permuted into degree-sorted space
__device__ float g_deg[NN];
__device__ float g_dinv[NN];
__device__ int   g_cnt[NN];                 // in-degree by original node id
__device__ int   g_cnt4[NN];                // padded in-degree by permuted id
__device__ int   g_rowstart[NN + 1];        // padded CSR rowstart (permuted space)
__device__ int   g_cursor[NN];
__device__ int   g_bsum[SCAN_BLOCKS + 32];
__device__ int   g_dbins[NBINS];
__device__ int   g_dcur[NBINS];
__device__ int   g_perm[NN];                // perm[g] = original id
__device__ int   g_rank[NN];                // rank[orig] = g
__device__ __align__(16) float2 g_adj[EPAD]; // (src_rank_as_float_bits, norm); pads are zero

// ---------------- normalization ----------------
__global__ void deg_hist_kernel(const int* __restrict__ src, const int* __restrict__ dst,
                                const float* __restrict__ w,
                                float* __restrict__ deg, int* __restrict__ cnt) {
    int e = blockIdx.x * blockDim.x + threadIdx.x;
    if (e >= EE) return;
    int s = src[e], d = dst[e];
    float ww = (s == d) ? 0.0f : w[e];
    if (ww != 0.0f) atomicAdd(&deg[s], ww);
    atomicAdd(&cnt[d], 1);
}

// fused: dinv + degree-bin histogram
__global__ void dinv_binhist_kernel(const float* __restrict__ deg, const int* __restrict__ cnt,
                                    float* __restrict__ dinv, int* __restrict__ dbins) {
    int i = blockIdx.x * blockDim.x + threadIdx.x;
    if (i >= NN) return;
    float d = deg[i];
    dinv[i] = (d > 0.0f) ? rsqrtf(d) : 0.0f;
    atomicAdd(&dbins[min(cnt[i], NBINS - 1)], 1);
}

__global__ void bin_scan_kernel(const int* __restrict__ dbins, int* __restrict__ dcur) {
    __shared__ int s[NBINS];
    int t = threadIdx.x;
    int v = dbins[t];
    s[t] = v;
    __syncthreads();
#pragma unroll
    for (int off = 1; off < NBINS; off <<= 1) {
        int tt = (t >= off) ? s[t - off] : 0;
        __syncthreads();
        s[t] += tt;
        __syncthreads();
    }
    dcur[t] = s[t] - v;
}

// fused: scatter nodes into degree order + emit padded counts in permuted space
__global__ void bin_scatter_kernel(const int* __restrict__ cnt, int* __restrict__ dcur,
                                   int* __restrict__ perm, int* __restrict__ rank,
                                   int* __restrict__ cnt4) {
    int i = blockIdx.x * blockDim.x + threadIdx.x;
    if (i >= NN) return;
    int c = cnt[i];
    int pos = atomicAdd(&dcur[min(c, NBINS - 1)], 1);
    perm[pos] = i;
    rank[i] = pos;
    cnt4[pos] = (c + 3) & ~3;   // pad to multiple of 4
}

// x_p[g] = x[perm[g]]
__global__ void permute_x_kernel(const float* __restrict__ x, const int* __restrict__ perm,
                                 float* __restrict__ xp) {
    unsigned tid = blockIdx.x * blockDim.x + threadIdx.x;
    unsigned g = tid >> 4;
    if (g >= NN) return;
    unsigned lane = tid & 15u;
    int n = perm[g];
    reinterpret_cast<float4*>(xp)[(size_t)g * 16 + lane] =
        reinterpret_cast<const float4*>(x)[(size_t)n * 16 + lane];
}

// ---------------- scan (exclusive) of cnt4 -> rowstart ----------------
__global__ void scan_block_kernel(const int* __restrict__ cnt, int* __restrict__ rowstart,
                                  int* __restrict__ bsum) {
    __shared__ int s[SCAN_TPB];
    int i = blockIdx.x * SCAN_TPB + threadIdx.x;
    int v = (i < NN) ? cnt[i] : 0;
    s[threadIdx.x] = v;
    __syncthreads();
#pragma unroll
    for (int off = 1; off < SCAN_TPB; off <<= 1) {
        int t = (threadIdx.x >= off) ? s[threadIdx.x - off] : 0;
        __syncthreads();
        s[threadIdx.x] += t;
        __syncthreads();
    }
    if (i <= NN) rowstart[i] = s[threadIdx.x] - v;
    if (threadIdx.x == SCAN_TPB - 1) bsum[blockIdx.x] = s[threadIdx.x];
}

__global__ void scan_sums_kernel(int* __restrict__ bsum) {
    __shared__ int s[128];
    int t = threadIdx.x;
    int v = (t < SCAN_BLOCKS) ? bsum[t] : 0;
    s[t] = v;
    __syncthreads();
#pragma unroll
    for (int off = 1; off < 128; off <<= 1) {
        int tt = (t >= off) ? s[t - off] : 0;
        __syncthreads();
        s[t] += tt;
        __syncthreads();
    }
    if (t < SCAN_BLOCKS) bsum[t] = s[t] - v;
}

__global__ void scan_add_kernel(int* __restrict__ rowstart, const int* __restrict__ bsum,
                                int* __restrict__ cursor) {
    int i = blockIdx.x * blockDim.x + threadIdx.x;
    if (i > NN) return;
    int r = rowstart[i] + bsum[i / SCAN_TPB];
    rowstart[i] = r;
    if (i < NN) cursor[i] = r;
}

// Scatter edges into padded permuted CSR; src stored as rank.
__global__ void scatter_kernel(const int* __restrict__ src, const int* __restrict__ dst,
                               const float* __restrict__ w, const float* __restrict__ dinv,
                               const int* __restrict__ rank,
                               int* __restrict__ cursor, float2* __restrict__ adj) {
    int e = blockIdx.x * blockDim.x + threadIdx.x;
    if (e >= EE) return;
    int s = src[e], d = dst[e];
    float ww = (s == d) ? 0.0f : w[e];
    float nrm = -dinv[s] * ww * dinv[d];
    int pos = atomicAdd(&cursor[rank[d]], 1);
    adj[pos] = make_float2(__int_as_float(rank[s]), nrm);
}

// ---------------- CSR gather propagation ----------------
// 16 lanes/node; rows 4-edge padded so adj loads are LDG.128 (2 edges each).
template <bool FIRST>
__global__ __launch_bounds__(256)
void prop16_kernel(const float* __restrict__ h, const float2* __restrict__ adj,
                   const int* __restrict__ rowstart, const float* __restrict__ t0,
                   float* __restrict__ out) {
    unsigned tid = blockIdx.x * blockDim.x + threadIdx.x;
    unsigned n = tid >> 4;
    if (n >= NN) return;
    unsigned lane = tid & 15u;
    int r0 = rowstart[n];
    int r1 = rowstart[n + 1];

    float4 acc = make_float4(0.f, 0.f, 0.f, 0.f);
    const float4* hb = reinterpret_cast<const float4*>(h);
    const float4* adjv = reinterpret_cast<const float4*>(adj);

#pragma unroll 2
    for (int e = r0; e < r1; e += 4) {
        float4 q0 = __ldg(&adjv[(e >> 1)]);       // edges e, e+1: (s0,w0,s1,w1)
        float4 q1 = __ldg(&adjv[(e >> 1) + 1]);   // edges e+2, e+3
        float4 v0 = hb[(size_t)__float_as_int(q0.x) * 16 + lane];
        float4 v1 = hb[(size_t)__float_as_int(q0.z) * 16 + lane];
        float4 v2 = hb[(size_t)__float_as_int(q1.x) * 16 + lane];
        float4 v3 = hb[(size_t)__float_as_int(q1.z) * 16 + lane];
        acc.x = fmaf(q0.y, v0.x, acc.x); acc.y = fmaf(q0.y, v0.y, acc.y);
        acc.z = fmaf(q0.y, v0.z, acc.z); acc.w = fmaf(q0.y, v0.w, acc.w);
        acc.x = fmaf(q0.w, v1.x, acc.x); acc.y = fmaf(q0.w, v1.y, acc.y);
        acc.z = fmaf(q0.w, v1.z, acc.z); acc.w = fmaf(q0.w, v1.w, acc.w);
        acc.x = fmaf(q1.y, v2.x, acc.x); acc.y = fmaf(q1.y, v2.y, acc.y);
        acc.z = fmaf(q1.y, v2.z, acc.z); acc.w = fmaf(q1.y, v2.w, acc.w);
        acc.x = fmaf(q1.w, v3.x, acc.x); acc.y = fmaf(q1.w, v3.y, acc.y);
        acc.z = fmaf(q1.w, v3.z, acc.z); acc.w = fmaf(q1.w, v3.w, acc.w);
    }

    size_t idx = (size_t)n * 16 + lane;
    if (FIRST) {
        reinterpret_cast<float4*>(out)[idx] = acc;
    } else {
        float4 t = reinterpret_cast<const float4*>(t0)[idx];
        reinterpret_cast<float4*>(out)[idx] =
            make_float4(2.0f * acc.x - t.x, 2.0f * acc.y - t.y,
                        2.0f * acc.z - t.z, 2.0f * acc.w - t.w);
    }
}

// ---------------- fused 8-way GEMM + bias + relu, packed f32x2 ----------------
// Tile 128 rows x 64 cols, 256 threads: tx = tid&3 (16 cols), ty = tid>>2 (2 rows).
// X tile stored with float4-granular rotate swizzle: chunk c4 of row r lives at
// column group (c4 + (r>>1)) & 15 -> conflict-free A-column reads, no padding.
struct TPtrs { const float* p[KK]; };

#define FMA2(a, v, w) asm("fma.rn.f32x2 %0, %1, %2, %0;" : "+l"(a) : "l"(v), "l"(w))
#define DUP2(d, f)    asm("mov.b64 %0, {%1, %1};" : "=l"(d) : "f"(f))
#define UNPK(lo, hi, a) asm("mov.b64 {%0, %1}, %2;" : "=f"(lo), "=f"(hi) : "l"(a))

__global__ __launch_bounds__(256)
void gemm8_kernel(TPtrs ts, const float* __restrict__ W,
                  const float* __restrict__ bias, float* __restrict__ out,
                  const int* __restrict__ operm) {
    __shared__ float Xs[128][DD];      // swizzled
    __shared__ float Ws[DD][DD];
    int tid = threadIdx.x;
    int row0 = blockIdx.x * 128;
    int tx = tid & 3, ty = tid >> 2;

    unsigned long long acc0[8], acc1[8];
#pragma unroll
    for (int i = 0; i < 8; i++) { acc0[i] = 0ull; acc1[i] = 0ull; }

    for (int k = 0; k < KK; ++k) {
        const float* X = ts.p[k];
        const float* Wp = W + (size_t)k * DD * DD;
#pragma unroll
        for (int i = 0; i < 4; i++) {
            int f4 = tid + i * 256;          // 1024 float4s of W
            int j = f4 >> 4, c4 = f4 & 15;
            reinterpret_cast<float4*>(&Ws[j][0])[c4] =
                reinterpret_cast<const float4*>(Wp)[f4];
        }
#pragma unroll
        for (int i = 0; i < 8; i++) {
            int f4 = tid + i * 256;          // 128 rows x 16 float4
            int r = f4 >> 4, c4 = f4 & 15;
            int sc4 = (c4 + (r >> 1)) & 15;  // swizzle
            int gr = row0 + r;
            float4 v = make_float4(0.f, 0.f, 0.f, 0.f);
            if (gr < NN) v = reinterpret_cast<const float4*>(X + (size_t)gr * DD)[c4];
            reinterpret_cast<float4*>(&Xs[r][0])[sc4] = v;
        }
        __syncthreads();

#pragma unroll 8
        for (int j = 0; j < DD; j++) {
            int sc4 = ((j >> 2) + ty) & 15;       // shared by both rows of this thread
            int col = sc4 * 4 + (j & 3);
            float a0 = Xs[ty * 2 + 0][col];
            float a1 = Xs[ty * 2 + 1][col];
            unsigned long long A0, A1;
            DUP2(A0, a0);
            DUP2(A1, a1);
            const ulonglong2* bp = reinterpret_cast<const ulonglong2*>(&Ws[j][tx * 16]);
            ulonglong2 b01 = bp[0], b23 = bp[1], b45 = bp[2], b67 = bp[3];
            FMA2(acc0[0], A0, b01.x); FMA2(acc0[1], A0, b01.y);
            FMA2(acc0[2], A0, b23.x); FMA2(acc0[3], A0, b23.y);
            FMA2(acc0[4], A0, b45.x); FMA2(acc0[5], A0, b45.y);
            FMA2(acc0[6], A0, b67.x); FMA2(acc0[7], A0, b67.y);
            FMA2(acc1[0], A1, b01.x); FMA2(acc1[1], A1, b01.y);
            FMA2(acc1[2], A1, b23.x); FMA2(acc1[3], A1, b23.y);
            FMA2(acc1[4], A1, b45.x); FMA2(acc1[5], A1, b45.y);
            FMA2(acc1[6], A1, b67.x); FMA2(acc1[7], A1, b67.y);
        }
        __syncthreads();
    }

    // epilogue: bias + relu (+ optional un-permute of the row)
    float bv[16];
#pragma unroll
    for (int q = 0; q < 4; q++) {
        float4 b4 = reinterpret_cast<const float4*>(bias)[tx * 4 + q];
        bv[q * 4 + 0] = b4.x; bv[q * 4 + 1] = b4.y;
        bv[q * 4 + 2] = b4.z; bv[q * 4 + 3] = b4.w;
    }
#pragma unroll
    for (int hh = 0; hh < 2; hh++) {
        int gr = row0 + ty * 2 + hh;
        if (gr >= NN) continue;
        int orow = operm ? operm[gr] : gr;
        unsigned long long* acc = hh ? acc1 : acc0;
#pragma unroll
        for (int q = 0; q < 4; q++) {
            float x0, x1, x2, x3;
            UNPK(x0, x1, acc[2 * q]);
            UNPK(x2, x3, acc[2 * q + 1]);
            float4 v;
            v.x = fmaxf(x0 + bv[q * 4 + 0], 0.f);
            v.y = fmaxf(x1 + bv[q * 4 + 1], 0.f);
            v.z = fmaxf(x2 + bv[q * 4 + 2], 0.f);
            v.w = fmaxf(x3 + bv[q * 4 + 3], 0.f);
            reinterpret_cast<float4*>(out + (size_t)orow * DD)[tx * 4 + q] = v;
        }
    }
}

// ---------------- launcher ----------------
extern "C" void kernel_launch(void* const* d_in, const int* in_sizes, int n_in,
                              void* d_out, int out_size) {
    const float* x  = (const float*)d_in[0];
    const int*   ei = (const int*)d_in[1];
    const float* ew = (const float*)d_in[2];
    const float* Wt = (const float*)d_in[3];
    const float* Bs = (const float*)d_in[4];
    const int* src = ei;
    const int* dst = ei + EE;

    float *Tbuf, *out1, *out2, *xp, *deg, *dinv;
    int *cnt, *cnt4, *rowstart, *cursor, *bsum, *dbins, *dcur, *perm, *rank;
    float2* adj;
    cudaGetSymbolAddress((void**)&Tbuf, g_T);
    cudaGetSymbolAddress((void**)&out1, g_out1);
    cudaGetSymbolAddress((void**)&out2, g_out2);
    cudaGetSymbolAddress((void**)&xp, g_xp);
    cudaGetSymbolAddress((void**)&deg, g_deg);
    cudaGetSymbolAddress((void**)&dinv, g_dinv);
    cudaGetSymbolAddress((void**)&cnt, g_cnt);
    cudaGetSymbolAddress((void**)&cnt4, g_cnt4);
    cudaGetSymbolAddress((void**)&rowstart, g_rowstart);
    cudaGetSymbolAddress((void**)&cursor, g_cursor);
    cudaGetSymbolAddress((void**)&bsum, g_bsum);
    cudaGetSymbolAddress((void**)&dbins, g_dbins);
    cudaGetSymbolAddress((void**)&dcur, g_dcur);
    cudaGetSymbolAddress((void**)&perm, g_perm);
    cudaGetSymbolAddress((void**)&rank, g_rank);
    cudaGetSymbolAddress((void**)&adj, g_adj);

    const size_t FB = (size_t)NN * DD;
    float* TB[7];
    for (int i = 0; i < 7; i++) TB[i] = Tbuf + (size_t)i * FB;

    const int T = 256;
    const int edgeBlocks = (EE + T - 1) / T;
    const int nodeBlocks = (NN + T - 1) / T;
    const int node1Blocks = (NN + 1 + T - 1) / T;
    const int propBlocks = (NN * 16 + T - 1) / T;
    const int gemmBlocks = (NN + 127) / 128;

    // --- setup: degrees, sort, padded permuted CSR, permuted x ---
    cudaMemsetAsync(deg, 0, NN * sizeof(float));
    cudaMemsetAsync(cnt, 0, NN * sizeof(int));
    cudaMemsetAsync(dbins, 0, NBINS * sizeof(int));
    cudaMemsetAsync(adj, 0, (size_t)EPAD * sizeof(float2));
    deg_hist_kernel<<<edgeBlocks, T>>>(src, dst, ew, deg, cnt);
    dinv_binhist_kernel<<<nodeBlocks, T>>>(deg, cnt, dinv, dbins);
    bin_scan_kernel<<<1, NBINS>>>(dbins, dcur);
    bin_scatter_kernel<<<nodeBlocks, T>>>(cnt, dcur, perm, rank, cnt4);
    scan_block_kernel<<<SCAN_BLOCKS, SCAN_TPB>>>(cnt4, rowstart, bsum);
    scan_sums_kernel<<<1, 128>>>(bsum);
    scan_add_kernel<<<node1Blocks, T>>>(rowstart, bsum, cursor);
    scatter_kernel<<<edgeBlocks, T>>>(src, dst, ew, dinv, rank, cursor, adj);
    permute_x_kernel<<<propBlocks, T>>>(x, perm, xp);

    // --- layers (all buffers in permuted space) ---
    const float* hin = xp;
    float* houts[3] = {out1, out2, (float*)d_out};

    for (int l = 0; l < LL; l++) {
        const float* Wl = Wt + (size_t)l * KK * DD * DD;
        prop16_kernel<true><<<propBlocks, T>>>(hin, adj, rowstart, nullptr, TB[0]);
        for (int k = 2; k < KK; k++) {
            const float* tin = TB[k - 2];
            const float* t0 = (k == 2) ? hin : TB[k - 3];
            prop16_kernel<false><<<propBlocks, T>>>(tin, adj, rowstart, t0, TB[k - 1]);
        }
        TPtrs ts;
        ts.p[0] = hin;
        for (int k = 1; k < KK; k++) ts.p[k] = TB[k - 1];
        const int* operm = (l == LL - 1) ? perm : nullptr;
        gemm8_kernel<<<gemmBlocks, T>>>(ts, Wl, Bs + (size_t)l * DD, houts[l], operm);
        hin = houts[l];
    }
}